// round 14
// baseline (speedup 1.0000x reference)
#include <cuda_runtime.h>
#include <cuda.h>
#include <cuda_fp16.h>
#include <cstdint>

#define N_Q   65536
#define N_P   16384
#define C_OUT 512
#define C_IN  1024
#define SEGS  4
#define QPS   (N_Q/SEGS)   // 16384
#define PPS   (N_P/SEGS)   // 4096

// ---------------- device scratch (referenced ONLY from device code) ----------------
__device__ float  g_x2[(size_t)N_P * C_OUT];      // 32 MB: relu(bn(feat_2 @ W2))
__device__ __half g_a1h[(size_t)N_Q * C_OUT];     // 64 MB: fp16 feat_1
__device__ __half g_a2h[(size_t)N_P * C_IN];      // 32 MB: fp16 feat_2
__device__ __half g_wt1[(size_t)C_OUT * C_OUT];   // W1^T [512,512] fp16
__device__ __half g_wt2[(size_t)C_OUT * C_IN];    // W2^T [512,1024] fp16
__device__ float4 g_p4[N_P];                      // packed points {x,y,z,|p|^2}
__device__ int    g_idx[N_Q * 3];
__device__ float  g_w[N_Q * 3];
__device__ float  g_s1[C_OUT], g_t1[C_OUT], g_s2[C_OUT], g_t2[C_OUT];

// ---------------- PTX helpers ----------------
__device__ __forceinline__ uint32_t smem_u32(const void* p) {
    uint32_t a;
    asm("{ .reg .u64 t; cvta.to.shared.u64 t, %1; cvt.u32.u64 %0, t; }" : "=r"(a) : "l"(p));
    return a;
}
__device__ __forceinline__ void mma_f16(float* d, const uint32_t* a, const uint32_t* b) {
    asm volatile(
        "mma.sync.aligned.m16n8k16.row.col.f32.f16.f16.f32 "
        "{%0,%1,%2,%3}, {%4,%5,%6,%7}, {%8,%9}, {%0,%1,%2,%3};"
        : "+f"(d[0]), "+f"(d[1]), "+f"(d[2]), "+f"(d[3])
        : "r"(a[0]), "r"(a[1]), "r"(a[2]), "r"(a[3]), "r"(b[0]), "r"(b[1]));
}
__device__ __forceinline__ void ldsm_x4(uint32_t& r0, uint32_t& r1, uint32_t& r2, uint32_t& r3,
                                        uint32_t addr) {
    asm volatile("ldmatrix.sync.aligned.m8n8.x4.shared.b16 {%0,%1,%2,%3}, [%4];"
                 : "=r"(r0), "=r"(r1), "=r"(r2), "=r"(r3) : "r"(addr));
}
__device__ __forceinline__ void mbar_init(uint32_t m, uint32_t cnt) {
    asm volatile("mbarrier.init.shared.b64 [%0], %1;" :: "r"(m), "r"(cnt) : "memory");
}
__device__ __forceinline__ void mbar_expect_tx(uint32_t m, uint32_t bytes) {
    asm volatile("mbarrier.arrive.expect_tx.shared.b64 _, [%0], %1;" :: "r"(m), "r"(bytes) : "memory");
}
__device__ __forceinline__ void mbar_wait(uint32_t m, uint32_t parity) {
    asm volatile(
        "{\n\t.reg .pred P;\n"
        "W_%=:\n\t"
        "mbarrier.try_wait.parity.acquire.cta.shared::cta.b64 P, [%0], %1, 0x989680;\n\t"
        "@!P bra W_%=;\n\t}"
        :: "r"(m), "r"(parity) : "memory");
}
__device__ __forceinline__ void tma_2d(uint32_t dst, const void* map, int x, int y, uint32_t mbar) {
    asm volatile(
        "cp.async.bulk.tensor.2d.shared::cta.global.tile.mbarrier::complete_tx::bytes "
        "[%0], [%1, {%2, %3}], [%4];"
        :: "r"(dst), "l"(map), "r"(x), "r"(y), "r"(mbar) : "memory");
}

// ---------------- prep kernels ----------------
__global__ void prep_scales_kernel(const float* __restrict__ b1, const float* __restrict__ g1,
                                   const float* __restrict__ be1, const float* __restrict__ m1,
                                   const float* __restrict__ v1,
                                   const float* __restrict__ b2, const float* __restrict__ g2,
                                   const float* __restrict__ be2, const float* __restrict__ m2,
                                   const float* __restrict__ v2)
{
    int j = threadIdx.x;
    float s1 = g1[j] * rsqrtf(v1[j] + 1e-5f);
    g_s1[j] = s1;
    g_t1[j] = fmaf(b1[j] - m1[j], s1, be1[j]);
    float s2 = g2[j] * rsqrtf(v2[j] + 1e-5f);
    g_s2[j] = s2;
    g_t2[j] = fmaf(b2[j] - m2[j], s2, be2[j]);
}

__global__ void prep_points_kernel(const float* __restrict__ p2)
{
    int i = blockIdx.x * 256 + threadIdx.x;
    float x = p2[3*i], y = p2[3*i+1], z = p2[3*i+2];
    float pp = __fadd_rn(__fadd_rn(__fmul_rn(x,x), __fmul_rn(y,y)), __fmul_rn(z,z));
    g_p4[i] = make_float4(x, y, z, pp);
}

// fp32 -> fp16 activation conversion (vectorized)
__global__ void cvt_h_kernel(const float4* __restrict__ in, int n4, int which)
{
    __half* __restrict__ dst = (which == 1) ? g_a1h : g_a2h;
    int i = blockIdx.x * 256 + threadIdx.x;
    if (i >= n4) return;
    float4 v = in[i];
    __half2 h0 = __floats2half2_rn(v.x, v.y);
    __half2 h1 = __floats2half2_rn(v.z, v.w);
    *(__half2*)(dst + (size_t)i * 4)     = h0;
    *(__half2*)(dst + (size_t)i * 4 + 2) = h1;
}

// W [K, 512] row-major -> g_wt{1,2} [512, K] row-major fp16 (device-symbol dst)
__global__ void transpose_kernel(const float* __restrict__ W, int K, int which)
{
    __half* __restrict__ Wt = (which == 1) ? g_wt1 : g_wt2;
    __shared__ float t[32][33];
    int n0 = blockIdx.x * 32, k0 = blockIdx.y * 32;
    int x = threadIdx.x, y = threadIdx.y;   // 32 x 8
    #pragma unroll
    for (int i = 0; i < 32; i += 8)
        t[y + i][x] = W[(size_t)(k0 + y + i) * C_OUT + n0 + x];
    __syncthreads();
    #pragma unroll
    for (int i = 0; i < 32; i += 8)
        Wt[(size_t)(n0 + y + i) * K + k0 + x] = __float2half_rn(t[x][y + i]);
}

// ---------------- merged fp16 mma.sync GEMM + BN + ReLU, TMA + ldmatrix, occ=2 --------
#define BK       64
#define NST      3
#define A_BYTES  (128 * 128)             // 128 rows x 64 halves = 16384 B
#define B_BYTES  (128 * 128)             // 16384 B
#define STAGE_B  (A_BYTES + B_BYTES)     // 32768
#define TX_BYTES STAGE_B
#define GEMM_SMEM (NST * STAGE_B + 1024 + 64)

__global__ void __launch_bounds__(256, 2)
gemm_mma_kernel(const __grid_constant__ CUtensorMap mA1,
                const __grid_constant__ CUtensorMap mB1,
                const __grid_constant__ CUtensorMap mA2,
                const __grid_constant__ CUtensorMap mB2,
                float* __restrict__ out)
{
    extern __shared__ __align__(16) char S[];

    const bool is1 = (blockIdx.y < (N_Q / 128));
    const CUtensorMap* pA = is1 ? &mA1 : &mA2;
    const CUtensorMap* pB = is1 ? &mB1 : &mB2;
    const float* __restrict__ scl = is1 ? g_s1 : g_s2;
    const float* __restrict__ sft = is1 ? g_t1 : g_t2;
    float* __restrict__ C = is1 ? out : g_x2;
    const int K  = is1 ? C_OUT : C_IN;
    const int bm = (is1 ? blockIdx.y : blockIdx.y - (N_Q / 128)) * 128;
    const int bn = blockIdx.x * 128;

    const uint32_t raw  = smem_u32(S);
    const uint32_t base = (raw + 1023u) & ~1023u;
    const uint32_t mb   = base + NST * STAGE_B;          // 3 mbarriers

    const int tid  = threadIdx.x;
    const int warp = tid >> 5;
    const int lane = tid & 31;
    const int wM = warp >> 2;        // 0..1
    const int wN = warp & 3;         // 0..3
    const int lq = lane >> 2;        // 0..7
    const int kk = lane & 3;         // 0..3

    // ldmatrix per-lane tile decomposition
    const int tl = lane >> 3;        // tile index 0..3
    const int tr = lane & 7;         // row within tile
    const uint32_t Xl = (uint32_t)tr << 4;               // swizzle xor for this lane
    const uint32_t aRowOff = (uint32_t)(wM * 64 + ((tl & 1) << 3) + tr) * 128;
    const uint32_t aColSel = (uint32_t)(tl >> 1) << 4;   // 0 or 16
    const uint32_t bRowOff0 = (uint32_t)(wN * 32 + ((tl >> 1) << 3) + tr) * 128;
    const uint32_t bColSel  = (uint32_t)(tl & 1) << 4;   // 0 or 16

    const int nchunk = K >> 6;       // K / 64

    if (tid == 0) {
        #pragma unroll
        for (int i = 0; i < NST; i++) mbar_init(mb + i * 8, 1);
    }
    __syncthreads();

    if (tid == 0) {
        #pragma unroll
        for (int i = 0; i < NST - 1; i++) {
            mbar_expect_tx(mb + i * 8, TX_BYTES);
            tma_2d(base + i * STAGE_B,           pA, i * BK, bm, mb + i * 8);
            tma_2d(base + i * STAGE_B + A_BYTES, pB, i * BK, bn, mb + i * 8);
        }
    }

    float acc[4][4][4];
    #pragma unroll
    for (int mt = 0; mt < 4; mt++)
        #pragma unroll
        for (int nt = 0; nt < 4; nt++)
            #pragma unroll
            for (int r = 0; r < 4; r++) acc[mt][nt][r] = 0.0f;

    int s = 0, ph = 0;
    for (int c = 0; c < nchunk; c++) {
        mbar_wait(mb + s * 8, ph);
        __syncthreads();                       // all warps done with stage being refilled

        if (tid == 0 && c + NST - 1 < nchunk) {
            int sl = s + NST - 1; if (sl >= NST) sl -= NST;
            mbar_expect_tx(mb + sl * 8, TX_BYTES);
            tma_2d(base + sl * STAGE_B,           pA, (c + NST - 1) * BK, bm, mb + sl * 8);
            tma_2d(base + sl * STAGE_B + A_BYTES, pB, (c + NST - 1) * BK, bn, mb + sl * 8);
        }

        const uint32_t At = base + s * STAGE_B;
        const uint32_t Bt = At + A_BYTES;

        #pragma unroll
        for (int ks = 0; ks < 4; ks++) {       // 4 k-steps of k16
            const uint32_t aCol = ((uint32_t)(ks * 32) + aColSel) ^ Xl;
            const uint32_t bCol = ((uint32_t)(ks * 32) + bColSel) ^ Xl;
            uint32_t a[4][4], b[4][2];
            #pragma unroll
            for (int mt = 0; mt < 4; mt++)
                ldsm_x4(a[mt][0], a[mt][1], a[mt][2], a[mt][3],
                        At + aRowOff + (uint32_t)(mt * 16 * 128) + aCol);
            #pragma unroll
            for (int np = 0; np < 2; np++)
                ldsm_x4(b[2*np][0], b[2*np][1], b[2*np+1][0], b[2*np+1][1],
                        Bt + bRowOff0 + (uint32_t)(np * 16 * 128) + bCol);
            #pragma unroll
            for (int mt = 0; mt < 4; mt++)
                #pragma unroll
                for (int nt = 0; nt < 4; nt++)
                    mma_f16(acc[mt][nt], a[mt], b[nt]);
        }
        if (++s >= NST) { s = 0; ph ^= 1; }
    }

    // epilogue: BN + ReLU, float2 stores
    const int colb = bn + wN * 32 + 2 * kk;
    float sc0[4], sc1[4], sh0[4], sh1[4];
    #pragma unroll
    for (int nt = 0; nt < 4; nt++) {
        int col = colb + nt * 8;
        sc0[nt] = __ldg(scl + col);     sc1[nt] = __ldg(scl + col + 1);
        sh0[nt] = __ldg(sft + col);     sh1[nt] = __ldg(sft + col + 1);
    }
    #pragma unroll
    for (int mt = 0; mt < 4; mt++) {
        const int r0 = bm + wM * 64 + mt * 16 + lq;
        #pragma unroll
        for (int nt = 0; nt < 4; nt++) {
            float2 v0, v1;
            v0.x = fmaxf(fmaf(acc[mt][nt][0], sc0[nt], sh0[nt]), 0.0f);
            v0.y = fmaxf(fmaf(acc[mt][nt][1], sc1[nt], sh1[nt]), 0.0f);
            v1.x = fmaxf(fmaf(acc[mt][nt][2], sc0[nt], sh0[nt]), 0.0f);
            v1.y = fmaxf(fmaf(acc[mt][nt][3], sc1[nt], sh1[nt]), 0.0f);
            *(float2*)(C + (size_t)r0 * C_OUT + colb + nt * 8)       = v0;
            *(float2*)(C + (size_t)(r0 + 8) * C_OUT + colb + nt * 8) = v1;
        }
    }
}

// ---------------- brute-force 3-NN, 4-way split scan per query (R10 proven) ----------
#define KNN_T 256
#define CHUNK 2048
#define NHALF 4

__global__ void __launch_bounds__(KNN_T)
knn_kernel(const float* __restrict__ point1)
{
    __shared__ float4 pts[CHUNK];            // 32 KB
    __shared__ float  me[NHALF-1][64][3];
    __shared__ int    mi[NHALF-1][64][3];

    const int ql  = threadIdx.x & 63;
    const int h   = threadIdx.x >> 6;        // 0..3
    const int qid = blockIdx.x * 64 + ql;
    const int seg = qid >> 14;

    float qx = point1[3*qid], qy = point1[3*qid+1], qz = point1[3*qid+2];
    float qq = __fadd_rn(__fadd_rn(__fmul_rn(qx,qx), __fmul_rn(qy,qy)), __fmul_rn(qz,qz));

    float e0 = 3.4e38f, e1 = 3.4e38f, e2 = 3.4e38f;
    int   i0 = 0, i1 = 0, i2 = 0;

    const float4* pb = g_p4 + seg * PPS;
    for (int ch = 0; ch < PPS; ch += CHUNK) {
        for (int j = threadIdx.x; j < CHUNK; j += KNN_T)
            pts[j] = pb[ch + j];
        __syncthreads();
        #pragma unroll 4
        for (int jj = 0; jj < CHUNK / NHALF; jj++) {
            int j = NHALF * jj + h;
            float4 p = pts[j];
            float m = __fmul_rn(qx, p.x);
            m = fmaf(qy, p.y, m);
            m = fmaf(qz, p.z, m);
            float t = __fadd_rn(qq, p.w);
            float d = fmaf(-2.0f, m, t);
            float e = fmaxf(d, 0.0f);
            if (e < e2) {
                int gj = ch + j;
                if (e < e1) {
                    e2 = e1; i2 = i1;
                    if (e < e0) { e1 = e0; i1 = i0; e0 = e; i0 = gj; }
                    else        { e1 = e;  i1 = gj; }
                } else { e2 = e; i2 = gj; }
            }
        }
        __syncthreads();
    }

    if (h > 0) {
        me[h-1][ql][0] = e0; me[h-1][ql][1] = e1; me[h-1][ql][2] = e2;
        mi[h-1][ql][0] = i0; mi[h-1][ql][1] = i1; mi[h-1][ql][2] = i2;
    }
    __syncthreads();
    if (h == 0) {
        float ce[12]; int ci[12]; bool used[12];
        ce[0] = e0; ce[1] = e1; ce[2] = e2;
        ci[0] = i0; ci[1] = i1; ci[2] = i2;
        #pragma unroll
        for (int g = 0; g < 3; g++) {
            #pragma unroll
            for (int t = 0; t < 3; t++) {
                ce[3 + g*3 + t] = me[g][ql][t];
                ci[3 + g*3 + t] = mi[g][ql][t];
            }
        }
        #pragma unroll
        for (int sx = 0; sx < 12; sx++) used[sx] = false;
        float se[3]; int si[3];
        #pragma unroll
        for (int t = 0; t < 3; t++) {
            int best = -1; float be = 3.5e38f; int bi = 0x7FFFFFFF;
            #pragma unroll
            for (int sx = 0; sx < 12; sx++) {
                if (used[sx]) continue;
                if (ce[sx] < be || (ce[sx] == be && ci[sx] < bi)) { be = ce[sx]; bi = ci[sx]; best = sx; }
            }
            used[best] = true;
            se[t] = be; si[t] = bi;
        }
        float r0 = 1.0f / (se[0] + 1e-8f);
        float r1 = 1.0f / (se[1] + 1e-8f);
        float r2 = 1.0f / (se[2] + 1e-8f);
        float s = __fadd_rn(__fadd_rn(r0, r1), r2);
        int base = seg * PPS;
        g_idx[3*qid]   = base + si[0];  g_w[3*qid]   = r0 / s;
        g_idx[3*qid+1] = base + si[1];  g_w[3*qid+1] = r1 / s;
        g_idx[3*qid+2] = base + si[2];  g_w[3*qid+2] = r2 / s;
    }
}

// ---------------- gather-interp + residual add (out already holds x1) ----------------
__global__ void interp_add_kernel(float* __restrict__ out)
{
    int gid = blockIdx.x * 256 + threadIdx.x;
    int row = gid >> 7;
    int c4  = gid & 127;
    int i0 = g_idx[3*row], i1 = g_idx[3*row+1], i2 = g_idx[3*row+2];
    float w0 = g_w[3*row], w1 = g_w[3*row+1], w2 = g_w[3*row+2];
    const float4* x2 = (const float4*)g_x2;
    float4 a = x2[(size_t)i0 * 128 + c4];
    float4 b = x2[(size_t)i1 * 128 + c4];
    float4 c = x2[(size_t)i2 * 128 + c4];
    float4* op = (float4*)out + ((size_t)row * 128 + c4);
    float4 o = *op;
    o.x += fmaf(w2, c.x, fmaf(w1, b.x, w0 * a.x));
    o.y += fmaf(w2, c.y, fmaf(w1, b.y, w0 * a.y));
    o.z += fmaf(w2, c.z, fmaf(w1, b.z, w0 * a.z));
    o.w += fmaf(w2, c.w, fmaf(w1, b.w, w0 * a.w));
    *op = o;
}

// ---------------- launch ----------------
typedef CUresult (*EncFn)(CUtensorMap*, CUtensorMapDataType, cuuint32_t, void*,
                          const cuuint64_t*, const cuuint64_t*, const cuuint32_t*,
                          const cuuint32_t*, CUtensorMapInterleave, CUtensorMapSwizzle,
                          CUtensorMapL2promotion, CUtensorMapFloatOOBfill);

static void encode_map_h(EncFn enc, CUtensorMap* m, const void* ptr,
                         unsigned long long d0, unsigned long long d1)
{
    cuuint64_t dims[2] = { (cuuint64_t)d0, (cuuint64_t)d1 };
    cuuint64_t str[1]  = { (cuuint64_t)(d0 * 2) };
    cuuint32_t box[2]  = { 64u, 128u };           // 64 fp16 = 128 B row (SW128)
    cuuint32_t es[2]   = { 1u, 1u };
    enc(m, CU_TENSOR_MAP_DATA_TYPE_FLOAT16, 2, (void*)ptr, dims, str, box, es,
        CU_TENSOR_MAP_INTERLEAVE_NONE, CU_TENSOR_MAP_SWIZZLE_128B,
        CU_TENSOR_MAP_L2_PROMOTION_L2_128B, CU_TENSOR_MAP_FLOAT_OOB_FILL_NONE);
}

extern "C" void kernel_launch(void* const* d_in, const int* in_sizes, int n_in,
                              void* d_out, int out_size)
{
    const float* point_1 = (const float*)d_in[0];
    const float* feat_1  = (const float*)d_in[1];
    const float* point_2 = (const float*)d_in[2];
    const float* feat_2  = (const float*)d_in[3];
    const float* W1  = (const float*)d_in[4];
    const float* b1  = (const float*)d_in[5];
    const float* g1  = (const float*)d_in[6];
    const float* be1 = (const float*)d_in[7];
    const float* m1  = (const float*)d_in[8];
    const float* v1  = (const float*)d_in[9];
    const float* W2  = (const float*)d_in[10];
    const float* b2  = (const float*)d_in[11];
    const float* g2  = (const float*)d_in[12];
    const float* be2 = (const float*)d_in[13];
    const float* m2  = (const float*)d_in[14];
    const float* v2  = (const float*)d_in[15];
    float* out = (float*)d_out;

    // tensor-map encoder via runtime entry point (no -lcuda dependency)
    void* fnp = nullptr;
    cudaDriverEntryPointQueryResult qres;
#if CUDART_VERSION >= 12050
    cudaGetDriverEntryPointByVersion("cuTensorMapEncodeTiled", &fnp, 12000,
                                     cudaEnableDefault, &qres);
#else
    cudaGetDriverEntryPoint("cuTensorMapEncodeTiled", &fnp, cudaEnableDefault, &qres);
#endif
    EncFn enc = (EncFn)fnp;

    void *pa1 = nullptr, *pa2 = nullptr, *pwt1 = nullptr, *pwt2 = nullptr;
    cudaGetSymbolAddress(&pa1,  g_a1h);
    cudaGetSymbolAddress(&pa2,  g_a2h);
    cudaGetSymbolAddress(&pwt1, g_wt1);
    cudaGetSymbolAddress(&pwt2, g_wt2);

    CUtensorMap mA1, mB1, mA2, mB2;
    encode_map_h(enc, &mA1, pa1,  C_OUT, N_Q);    // A1h [65536, 512]
    encode_map_h(enc, &mB1, pwt1, C_OUT, C_OUT);  // Wt1 [512, 512]
    encode_map_h(enc, &mA2, pa2,  C_IN,  N_P);    // A2h [16384, 1024]
    encode_map_h(enc, &mB2, pwt2, C_IN,  C_OUT);  // Wt2 [512, 1024]

    cudaFuncSetAttribute(gemm_mma_kernel, cudaFuncAttributeMaxDynamicSharedMemorySize, GEMM_SMEM);

    // Streams/events created ONCE (first call = uncaptured correctness run), so the
    // driver memory they occupy is inside the harness's pre-capture baseline and
    // nothing is allocated during capture. Every call launches identical work.
    static cudaStream_t s1 = nullptr, s2 = nullptr;
    static cudaEvent_t eFork = nullptr, eJoin = nullptr, eCvt1 = nullptr;
    if (s1 == nullptr) {
        cudaStreamCreateWithFlags(&s1, cudaStreamNonBlocking);
        cudaStreamCreateWithFlags(&s2, cudaStreamNonBlocking);
        cudaEventCreateWithFlags(&eFork, cudaEventDisableTiming);
        cudaEventCreateWithFlags(&eJoin, cudaEventDisableTiming);
        cudaEventCreateWithFlags(&eCvt1, cudaEventDisableTiming);
    }

    cudaEventRecord(eFork, 0);
    cudaStreamWaitEvent(s1, eFork, 0);
    cudaStreamWaitEvent(s2, eFork, 0);

    // s1: points -> knn (independent of GEMM spine)
    prep_points_kernel<<<N_P / 256, 256, 0, s1>>>(point_2);
    knn_kernel<<<N_Q / 64, KNN_T, 0, s1>>>(point_1);
    cudaEventRecord(eJoin, s1);

    // s2: W1 transpose + feat_1 -> fp16 (GEMM1 inputs)
    transpose_kernel<<<dim3(16, C_OUT / 32), dim3(32, 8), 0, s2>>>(W1, C_OUT, 1);
    cvt_h_kernel<<<(N_Q * C_OUT / 4) / 256, 256, 0, s2>>>((const float4*)feat_1, N_Q * C_OUT / 4, 1);
    cudaEventRecord(eCvt1, s2);

    // main: scales, W2, feat_2 -> merged GEMM (waits on s2 for GEMM1 inputs)
    prep_scales_kernel<<<1, C_OUT>>>(b1, g1, be1, m1, v1, b2, g2, be2, m2, v2);
    transpose_kernel<<<dim3(16, C_IN / 32), dim3(32, 8)>>>(W2, C_IN, 2);
    cvt_h_kernel<<<(N_P * C_IN / 4) / 256, 256>>>((const float4*)feat_2, N_P * C_IN / 4, 2);

    cudaStreamWaitEvent(0, eCvt1, 0);
    gemm_mma_kernel<<<dim3(C_OUT / 128, N_Q / 128 + N_P / 128), 256, GEMM_SMEM>>>(
        mA1, mB1, mA2, mB2, out);

    // join: interp needs knn results + both GEMM outputs
    cudaStreamWaitEvent(0, eJoin, 0);
    interp_add_kernel<<<(N_Q * (C_OUT / 4)) / 256, 256>>>(out);
}

// round 15
// speedup vs baseline: 1.4438x; 1.4438x over previous
#include <cuda_runtime.h>
#include <cuda.h>
#include <cuda_fp16.h>
#include <cstdint>

#define N_Q   65536
#define N_P   16384
#define C_OUT 512
#define C_IN  1024
#define SEGS  4
#define QPS   (N_Q/SEGS)   // 16384
#define PPS   (N_P/SEGS)   // 4096

// ---------------- device scratch (referenced ONLY from device code) ----------------
__device__ float  g_x2[(size_t)N_P * C_OUT];      // 32 MB: relu(bn(feat_2 @ W2))
__device__ __half g_a1h[(size_t)N_Q * C_OUT];     // 64 MB: fp16 feat_1
__device__ __half g_a2h[(size_t)N_P * C_IN];      // 32 MB: fp16 feat_2
__device__ __half g_wt1[(size_t)C_OUT * C_OUT];   // W1^T [512,512] fp16
__device__ __half g_wt2[(size_t)C_OUT * C_IN];    // W2^T [512,1024] fp16
__device__ float4 g_p4[N_P];                      // packed points {x,y,z,|p|^2}
__device__ int    g_idx[N_Q * 3];
__device__ float  g_w[N_Q * 3];
__device__ float  g_s1[C_OUT], g_t1[C_OUT], g_s2[C_OUT], g_t2[C_OUT];

// ---------------- PTX helpers ----------------
__device__ __forceinline__ uint32_t smem_u32(const void* p) {
    uint32_t a;
    asm("{ .reg .u64 t; cvta.to.shared.u64 t, %1; cvt.u32.u64 %0, t; }" : "=r"(a) : "l"(p));
    return a;
}
__device__ __forceinline__ void mma_f16(float* d, const uint32_t* a, const uint32_t* b) {
    asm volatile(
        "mma.sync.aligned.m16n8k16.row.col.f32.f16.f16.f32 "
        "{%0,%1,%2,%3}, {%4,%5,%6,%7}, {%8,%9}, {%0,%1,%2,%3};"
        : "+f"(d[0]), "+f"(d[1]), "+f"(d[2]), "+f"(d[3])
        : "r"(a[0]), "r"(a[1]), "r"(a[2]), "r"(a[3]), "r"(b[0]), "r"(b[1]));
}
__device__ __forceinline__ void ldsm_x4(uint32_t& r0, uint32_t& r1, uint32_t& r2, uint32_t& r3,
                                        uint32_t addr) {
    asm volatile("ldmatrix.sync.aligned.m8n8.x4.shared.b16 {%0,%1,%2,%3}, [%4];"
                 : "=r"(r0), "=r"(r1), "=r"(r2), "=r"(r3) : "r"(addr));
}
__device__ __forceinline__ void mbar_init(uint32_t m, uint32_t cnt) {
    asm volatile("mbarrier.init.shared.b64 [%0], %1;" :: "r"(m), "r"(cnt) : "memory");
}
__device__ __forceinline__ void mbar_expect_tx(uint32_t m, uint32_t bytes) {
    asm volatile("mbarrier.arrive.expect_tx.shared.b64 _, [%0], %1;" :: "r"(m), "r"(bytes) : "memory");
}
__device__ __forceinline__ void mbar_wait(uint32_t m, uint32_t parity) {
    asm volatile(
        "{\n\t.reg .pred P;\n"
        "W_%=:\n\t"
        "mbarrier.try_wait.parity.acquire.cta.shared::cta.b64 P, [%0], %1, 0x989680;\n\t"
        "@!P bra W_%=;\n\t}"
        :: "r"(m), "r"(parity) : "memory");
}
__device__ __forceinline__ void tma_2d(uint32_t dst, const void* map, int x, int y, uint32_t mbar) {
    asm volatile(
        "cp.async.bulk.tensor.2d.shared::cta.global.tile.mbarrier::complete_tx::bytes "
        "[%0], [%1, {%2, %3}], [%4];"
        :: "r"(dst), "l"(map), "r"(x), "r"(y), "r"(mbar) : "memory");
}

// ---------------- prep kernels ----------------
__global__ void prep_scales_kernel(const float* __restrict__ b1, const float* __restrict__ g1,
                                   const float* __restrict__ be1, const float* __restrict__ m1,
                                   const float* __restrict__ v1,
                                   const float* __restrict__ b2, const float* __restrict__ g2,
                                   const float* __restrict__ be2, const float* __restrict__ m2,
                                   const float* __restrict__ v2)
{
    int j = threadIdx.x;
    float s1 = g1[j] * rsqrtf(v1[j] + 1e-5f);
    g_s1[j] = s1;
    g_t1[j] = fmaf(b1[j] - m1[j], s1, be1[j]);
    float s2 = g2[j] * rsqrtf(v2[j] + 1e-5f);
    g_s2[j] = s2;
    g_t2[j] = fmaf(b2[j] - m2[j], s2, be2[j]);
}

__global__ void prep_points_kernel(const float* __restrict__ p2)
{
    int i = blockIdx.x * 256 + threadIdx.x;
    float x = p2[3*i], y = p2[3*i+1], z = p2[3*i+2];
    float pp = __fadd_rn(__fadd_rn(__fmul_rn(x,x), __fmul_rn(y,y)), __fmul_rn(z,z));
    g_p4[i] = make_float4(x, y, z, pp);
}

// fp32 -> fp16 activation conversion (vectorized)
__global__ void cvt_h_kernel(const float4* __restrict__ in, int n4, int which)
{
    __half* __restrict__ dst = (which == 1) ? g_a1h : g_a2h;
    int i = blockIdx.x * 256 + threadIdx.x;
    if (i >= n4) return;
    float4 v = in[i];
    __half2 h0 = __floats2half2_rn(v.x, v.y);
    __half2 h1 = __floats2half2_rn(v.z, v.w);
    *(__half2*)(dst + (size_t)i * 4)     = h0;
    *(__half2*)(dst + (size_t)i * 4 + 2) = h1;
}

// W [K, 512] row-major -> g_wt{1,2} [512, K] row-major fp16 (device-symbol dst)
__global__ void transpose_kernel(const float* __restrict__ W, int K, int which)
{
    __half* __restrict__ Wt = (which == 1) ? g_wt1 : g_wt2;
    __shared__ float t[32][33];
    int n0 = blockIdx.x * 32, k0 = blockIdx.y * 32;
    int x = threadIdx.x, y = threadIdx.y;   // 32 x 8
    #pragma unroll
    for (int i = 0; i < 32; i += 8)
        t[y + i][x] = W[(size_t)(k0 + y + i) * C_OUT + n0 + x];
    __syncthreads();
    #pragma unroll
    for (int i = 0; i < 32; i += 8)
        Wt[(size_t)(n0 + y + i) * K + k0 + x] = __float2half_rn(t[x][y + i]);
}

// ---------------- fp16 mma.sync GEMM + BN + ReLU, TMA + ldmatrix, occ=2 ----------------
// CTA tile 128x128, 8 warps as 2(M) x 4(N), warp tile 64x32. BK=64 (fp16), NST=3.
#define BK       64
#define NST      3
#define A_BYTES  (128 * 128)             // 128 rows x 64 halves = 16384 B
#define B_BYTES  (128 * 128)             // 16384 B
#define STAGE_B  (A_BYTES + B_BYTES)     // 32768
#define TX_BYTES STAGE_B
#define GEMM_SMEM (NST * STAGE_B + 1024 + 64)

__global__ void __launch_bounds__(256, 2)
gemm_mma_kernel(const __grid_constant__ CUtensorMap mA,
                const __grid_constant__ CUtensorMap mB,
                float* __restrict__ out, int K, int which)
{
    extern __shared__ __align__(16) char S[];

    const bool is1 = (which == 1);
    const float* __restrict__ scl = is1 ? g_s1 : g_s2;
    const float* __restrict__ sft = is1 ? g_t1 : g_t2;
    float* __restrict__ C = is1 ? out : g_x2;
    const int bm = blockIdx.y * 128;
    const int bn = blockIdx.x * 128;

    const uint32_t raw  = smem_u32(S);
    const uint32_t base = (raw + 1023u) & ~1023u;
    const uint32_t mb   = base + NST * STAGE_B;          // 3 mbarriers

    const int tid  = threadIdx.x;
    const int warp = tid >> 5;
    const int lane = tid & 31;
    const int wM = warp >> 2;        // 0..1
    const int wN = warp & 3;         // 0..3
    const int lq = lane >> 2;        // 0..7
    const int kk = lane & 3;         // 0..3

    // ldmatrix per-lane tile decomposition
    const int tl = lane >> 3;        // tile index 0..3
    const int tr = lane & 7;         // row within tile
    const uint32_t Xl = (uint32_t)tr << 4;               // swizzle xor for this lane
    const uint32_t aRowOff = (uint32_t)(wM * 64 + ((tl & 1) << 3) + tr) * 128;
    const uint32_t aColSel = (uint32_t)(tl >> 1) << 4;   // 0 or 16
    const uint32_t bRowOff0 = (uint32_t)(wN * 32 + ((tl >> 1) << 3) + tr) * 128;
    const uint32_t bColSel  = (uint32_t)(tl & 1) << 4;   // 0 or 16

    const int nchunk = K >> 6;       // K / 64

    if (tid == 0) {
        #pragma unroll
        for (int i = 0; i < NST; i++) mbar_init(mb + i * 8, 1);
    }
    __syncthreads();

    if (tid == 0) {
        #pragma unroll
        for (int i = 0; i < NST - 1; i++) {
            mbar_expect_tx(mb + i * 8, TX_BYTES);
            tma_2d(base + i * STAGE_B,           &mA, i * BK, bm, mb + i * 8);
            tma_2d(base + i * STAGE_B + A_BYTES, &mB, i * BK, bn, mb + i * 8);
        }
    }

    float acc[4][4][4];
    #pragma unroll
    for (int mt = 0; mt < 4; mt++)
        #pragma unroll
        for (int nt = 0; nt < 4; nt++)
            #pragma unroll
            for (int r = 0; r < 4; r++) acc[mt][nt][r] = 0.0f;

    int s = 0, ph = 0;
    for (int c = 0; c < nchunk; c++) {
        mbar_wait(mb + s * 8, ph);
        __syncthreads();                       // all warps done with stage being refilled

        if (tid == 0 && c + NST - 1 < nchunk) {
            int sl = s + NST - 1; if (sl >= NST) sl -= NST;
            mbar_expect_tx(mb + sl * 8, TX_BYTES);
            tma_2d(base + sl * STAGE_B,           &mA, (c + NST - 1) * BK, bm, mb + sl * 8);
            tma_2d(base + sl * STAGE_B + A_BYTES, &mB, (c + NST - 1) * BK, bn, mb + sl * 8);
        }

        const uint32_t At = base + s * STAGE_B;
        const uint32_t Bt = At + A_BYTES;

        #pragma unroll
        for (int ks = 0; ks < 4; ks++) {       // 4 k-steps of k16
            const uint32_t aCol = ((uint32_t)(ks * 32) + aColSel) ^ Xl;
            const uint32_t bCol = ((uint32_t)(ks * 32) + bColSel) ^ Xl;
            uint32_t a[4][4], b[4][2];
            #pragma unroll
            for (int mt = 0; mt < 4; mt++)
                ldsm_x4(a[mt][0], a[mt][1], a[mt][2], a[mt][3],
                        At + aRowOff + (uint32_t)(mt * 16 * 128) + aCol);
            #pragma unroll
            for (int np = 0; np < 2; np++)
                ldsm_x4(b[2*np][0], b[2*np][1], b[2*np+1][0], b[2*np+1][1],
                        Bt + bRowOff0 + (uint32_t)(np * 16 * 128) + bCol);
            #pragma unroll
            for (int mt = 0; mt < 4; mt++)
                #pragma unroll
                for (int nt = 0; nt < 4; nt++)
                    mma_f16(acc[mt][nt], a[mt], b[nt]);
        }
        if (++s >= NST) { s = 0; ph ^= 1; }
    }

    // epilogue: BN + ReLU, float2 stores
    const int colb = bn + wN * 32 + 2 * kk;
    float sc0[4], sc1[4], sh0[4], sh1[4];
    #pragma unroll
    for (int nt = 0; nt < 4; nt++) {
        int col = colb + nt * 8;
        sc0[nt] = __ldg(scl + col);     sc1[nt] = __ldg(scl + col + 1);
        sh0[nt] = __ldg(sft + col);     sh1[nt] = __ldg(sft + col + 1);
    }
    #pragma unroll
    for (int mt = 0; mt < 4; mt++) {
        const int r0 = bm + wM * 64 + mt * 16 + lq;
        #pragma unroll
        for (int nt = 0; nt < 4; nt++) {
            float2 v0, v1;
            v0.x = fmaxf(fmaf(acc[mt][nt][0], sc0[nt], sh0[nt]), 0.0f);
            v0.y = fmaxf(fmaf(acc[mt][nt][1], sc1[nt], sh1[nt]), 0.0f);
            v1.x = fmaxf(fmaf(acc[mt][nt][2], sc0[nt], sh0[nt]), 0.0f);
            v1.y = fmaxf(fmaf(acc[mt][nt][3], sc1[nt], sh1[nt]), 0.0f);
            *(float2*)(C + (size_t)r0 * C_OUT + colb + nt * 8)       = v0;
            *(float2*)(C + (size_t)(r0 + 8) * C_OUT + colb + nt * 8) = v1;
        }
    }
}

// ---------------- brute-force 3-NN, 4-way split scan per query (R10/R12 proven) ------
#define KNN_T 256
#define CHUNK 2048
#define NHALF 4

__global__ void __launch_bounds__(KNN_T)
knn_kernel(const float* __restrict__ point1)
{
    __shared__ float4 pts[CHUNK];            // 32 KB
    __shared__ float  me[NHALF-1][64][3];
    __shared__ int    mi[NHALF-1][64][3];

    const int ql  = threadIdx.x & 63;
    const int h   = threadIdx.x >> 6;        // 0..3
    const int qid = blockIdx.x * 64 + ql;
    const int seg = qid >> 14;

    float qx = point1[3*qid], qy = point1[3*qid+1], qz = point1[3*qid+2];
    float qq = __fadd_rn(__fadd_rn(__fmul_rn(qx,qx), __fmul_rn(qy,qy)), __fmul_rn(qz,qz));

    float e0 = 3.4e38f, e1 = 3.4e38f, e2 = 3.4e38f;
    int   i0 = 0, i1 = 0, i2 = 0;

    const float4* pb = g_p4 + seg * PPS;
    for (int ch = 0; ch < PPS; ch += CHUNK) {
        for (int j = threadIdx.x; j < CHUNK; j += KNN_T)
            pts[j] = pb[ch + j];
        __syncthreads();
        #pragma unroll 4
        for (int jj = 0; jj < CHUNK / NHALF; jj++) {
            int j = NHALF * jj + h;
            float4 p = pts[j];
            float m = __fmul_rn(qx, p.x);
            m = fmaf(qy, p.y, m);
            m = fmaf(qz, p.z, m);
            float t = __fadd_rn(qq, p.w);
            float d = fmaf(-2.0f, m, t);
            float e = fmaxf(d, 0.0f);
            if (e < e2) {
                int gj = ch + j;
                if (e < e1) {
                    e2 = e1; i2 = i1;
                    if (e < e0) { e1 = e0; i1 = i0; e0 = e; i0 = gj; }
                    else        { e1 = e;  i1 = gj; }
                } else { e2 = e; i2 = gj; }
            }
        }
        __syncthreads();
    }

    if (h > 0) {
        me[h-1][ql][0] = e0; me[h-1][ql][1] = e1; me[h-1][ql][2] = e2;
        mi[h-1][ql][0] = i0; mi[h-1][ql][1] = i1; mi[h-1][ql][2] = i2;
    }
    __syncthreads();
    if (h == 0) {
        float ce[12]; int ci[12]; bool used[12];
        ce[0] = e0; ce[1] = e1; ce[2] = e2;
        ci[0] = i0; ci[1] = i1; ci[2] = i2;
        #pragma unroll
        for (int g = 0; g < 3; g++) {
            #pragma unroll
            for (int t = 0; t < 3; t++) {
                ce[3 + g*3 + t] = me[g][ql][t];
                ci[3 + g*3 + t] = mi[g][ql][t];
            }
        }
        #pragma unroll
        for (int sx = 0; sx < 12; sx++) used[sx] = false;
        float se[3]; int si[3];
        #pragma unroll
        for (int t = 0; t < 3; t++) {
            int best = -1; float be = 3.5e38f; int bi = 0x7FFFFFFF;
            #pragma unroll
            for (int sx = 0; sx < 12; sx++) {
                if (used[sx]) continue;
                if (ce[sx] < be || (ce[sx] == be && ci[sx] < bi)) { be = ce[sx]; bi = ci[sx]; best = sx; }
            }
            used[best] = true;
            se[t] = be; si[t] = bi;
        }
        float r0 = 1.0f / (se[0] + 1e-8f);
        float r1 = 1.0f / (se[1] + 1e-8f);
        float r2 = 1.0f / (se[2] + 1e-8f);
        float s = __fadd_rn(__fadd_rn(r0, r1), r2);
        int base = seg * PPS;
        g_idx[3*qid]   = base + si[0];  g_w[3*qid]   = r0 / s;
        g_idx[3*qid+1] = base + si[1];  g_w[3*qid+1] = r1 / s;
        g_idx[3*qid+2] = base + si[2];  g_w[3*qid+2] = r2 / s;
    }
}

// ---------------- gather-interp + residual add (out already holds x1) ----------------
__global__ void interp_add_kernel(float* __restrict__ out)
{
    int gid = blockIdx.x * 256 + threadIdx.x;
    int row = gid >> 7;
    int c4  = gid & 127;
    int i0 = g_idx[3*row], i1 = g_idx[3*row+1], i2 = g_idx[3*row+2];
    float w0 = g_w[3*row], w1 = g_w[3*row+1], w2 = g_w[3*row+2];
    const float4* x2 = (const float4*)g_x2;
    float4 a = x2[(size_t)i0 * 128 + c4];
    float4 b = x2[(size_t)i1 * 128 + c4];
    float4 c = x2[(size_t)i2 * 128 + c4];
    float4* op = (float4*)out + ((size_t)row * 128 + c4);
    float4 o = *op;
    o.x += fmaf(w2, c.x, fmaf(w1, b.x, w0 * a.x));
    o.y += fmaf(w2, c.y, fmaf(w1, b.y, w0 * a.y));
    o.z += fmaf(w2, c.z, fmaf(w1, b.z, w0 * a.z));
    o.w += fmaf(w2, c.w, fmaf(w1, b.w, w0 * a.w));
    *op = o;
}

// ---------------- launch ----------------
typedef CUresult (*EncFn)(CUtensorMap*, CUtensorMapDataType, cuuint32_t, void*,
                          const cuuint64_t*, const cuuint64_t*, const cuuint32_t*,
                          const cuuint32_t*, CUtensorMapInterleave, CUtensorMapSwizzle,
                          CUtensorMapL2promotion, CUtensorMapFloatOOBfill);

static void encode_map_h(EncFn enc, CUtensorMap* m, const void* ptr,
                         unsigned long long d0, unsigned long long d1)
{
    cuuint64_t dims[2] = { (cuuint64_t)d0, (cuuint64_t)d1 };
    cuuint64_t str[1]  = { (cuuint64_t)(d0 * 2) };
    cuuint32_t box[2]  = { 64u, 128u };           // 64 fp16 = 128 B row (SW128)
    cuuint32_t es[2]   = { 1u, 1u };
    enc(m, CU_TENSOR_MAP_DATA_TYPE_FLOAT16, 2, (void*)ptr, dims, str, box, es,
        CU_TENSOR_MAP_INTERLEAVE_NONE, CU_TENSOR_MAP_SWIZZLE_128B,
        CU_TENSOR_MAP_L2_PROMOTION_L2_128B, CU_TENSOR_MAP_FLOAT_OOB_FILL_NONE);
}

extern "C" void kernel_launch(void* const* d_in, const int* in_sizes, int n_in,
                              void* d_out, int out_size)
{
    const float* point_1 = (const float*)d_in[0];
    const float* feat_1  = (const float*)d_in[1];
    const float* point_2 = (const float*)d_in[2];
    const float* feat_2  = (const float*)d_in[3];
    const float* W1  = (const float*)d_in[4];
    const float* b1  = (const float*)d_in[5];
    const float* g1  = (const float*)d_in[6];
    const float* be1 = (const float*)d_in[7];
    const float* m1  = (const float*)d_in[8];
    const float* v1  = (const float*)d_in[9];
    const float* W2  = (const float*)d_in[10];
    const float* b2  = (const float*)d_in[11];
    const float* g2  = (const float*)d_in[12];
    const float* be2 = (const float*)d_in[13];
    const float* m2  = (const float*)d_in[14];
    const float* v2  = (const float*)d_in[15];
    float* out = (float*)d_out;

    // tensor-map encoder via runtime entry point (no -lcuda dependency)
    void* fnp = nullptr;
    cudaDriverEntryPointQueryResult qres;
#if CUDART_VERSION >= 12050
    cudaGetDriverEntryPointByVersion("cuTensorMapEncodeTiled", &fnp, 12000,
                                     cudaEnableDefault, &qres);
#else
    cudaGetDriverEntryPoint("cuTensorMapEncodeTiled", &fnp, cudaEnableDefault, &qres);
#endif
    EncFn enc = (EncFn)fnp;

    void *pa1 = nullptr, *pa2 = nullptr, *pwt1 = nullptr, *pwt2 = nullptr;
    cudaGetSymbolAddress(&pa1,  g_a1h);
    cudaGetSymbolAddress(&pa2,  g_a2h);
    cudaGetSymbolAddress(&pwt1, g_wt1);
    cudaGetSymbolAddress(&pwt2, g_wt2);

    CUtensorMap mA1, mB1, mA2, mB2;
    encode_map_h(enc, &mA1, pa1,  C_OUT, N_Q);    // A1h [65536, 512]
    encode_map_h(enc, &mB1, pwt1, C_OUT, C_OUT);  // Wt1 [512, 512]
    encode_map_h(enc, &mA2, pa2,  C_IN,  N_P);    // A2h [16384, 1024]
    encode_map_h(enc, &mB2, pwt2, C_IN,  C_OUT);  // Wt2 [512, 1024]

    cudaFuncSetAttribute(gemm_mma_kernel, cudaFuncAttributeMaxDynamicSharedMemorySize, GEMM_SMEM);

    // R12-proven resource pattern: ONE fresh side stream + TWO events per call.
    cudaStream_t s1;
    cudaStreamCreateWithFlags(&s1, cudaStreamNonBlocking);
    cudaEvent_t eFork, eJoin;
    cudaEventCreateWithFlags(&eFork, cudaEventDisableTiming);
    cudaEventCreateWithFlags(&eJoin, cudaEventDisableTiming);

    cudaEventRecord(eFork, 0);
    cudaStreamWaitEvent(s1, eFork, 0);

    // side stream: points -> knn -> cvt1 (GEMM1's A operand), all independent of GEMM2
    prep_points_kernel<<<N_P / 256, 256, 0, s1>>>(point_2);
    knn_kernel<<<N_Q / 64, KNN_T, 0, s1>>>(point_1);
    cvt_h_kernel<<<(N_Q * C_OUT / 4) / 256, 256, 0, s1>>>((const float4*)feat_1, N_Q * C_OUT / 4, 1);
    cudaEventRecord(eJoin, s1);

    // main stream: scales, weights, feat_2 -> GEMM2 (fills g_x2)
    prep_scales_kernel<<<1, C_OUT>>>(b1, g1, be1, m1, v1, b2, g2, be2, m2, v2);
    transpose_kernel<<<dim3(16, C_IN / 32), dim3(32, 8)>>>(W2, C_IN, 2);
    transpose_kernel<<<dim3(16, C_OUT / 32), dim3(32, 8)>>>(W1, C_OUT, 1);
    cvt_h_kernel<<<(N_P * C_IN / 4) / 256, 256>>>((const float4*)feat_2, N_P * C_IN / 4, 2);
    gemm_mma_kernel<<<dim3(C_OUT / 128, N_P / 128), 256, GEMM_SMEM>>>(mA2, mB2, out, C_IN, 2);

    // join once: GEMM1 needs cvt1 (and interp later needs knn, already covered)
    cudaStreamWaitEvent(0, eJoin, 0);
    gemm_mma_kernel<<<dim3(C_OUT / 128, N_Q / 128), 256, GEMM_SMEM>>>(mA1, mB1, out, C_OUT, 1);

    // interp: needs knn results (eJoin, waited) + g_x2 (GEMM2, same stream) + out (GEMM1)
    interp_add_kernel<<<(N_Q * (C_OUT / 4)) / 256, 256>>>(out);
}